// round 1
// baseline (speedup 1.0000x reference)
#include <cuda_runtime.h>
#include <cuda_bf16.h>

// Scratch (allocation-free rule: __device__ globals)
__device__ float g_partialC[96 * 1024];  // stage-1 C partial sums
__device__ float g_SC[1024];             // S_C[k*4+l]
__device__ float g_SX[128 * 64];         // S_x[b*64 + h*8 + w]

// ---------------------------------------------------------------------------
// Kernel 1: partial reduce of C over (i,j). C layout [3072 rows][1024 cols],
// cols contiguous. Each block reduces 32 rows with float4 per-thread partials.
// ---------------------------------------------------------------------------
__global__ void sumC_partial_kernel(const float* __restrict__ C) {
    const int t = threadIdx.x;           // 0..255 -> float4 column
    const int p = blockIdx.x;            // 0..95
    const float4* __restrict__ C4 = (const float4*)C;  // 256 float4 per row
    float4 acc = make_float4(0.f, 0.f, 0.f, 0.f);
    const int m0 = p * 32;
#pragma unroll 8
    for (int q = 0; q < 32; ++q) {
        float4 v = C4[(m0 + q) * 256 + t];
        acc.x += v.x; acc.y += v.y; acc.z += v.z; acc.w += v.w;
    }
    ((float4*)g_partialC)[p * 256 + t] = acc;
}

// ---------------------------------------------------------------------------
// Kernel 2: fold 96 partials -> S_C. 4 blocks x 256 threads.
// ---------------------------------------------------------------------------
__global__ void sumC_final_kernel() {
    const int t = blockIdx.x * 256 + threadIdx.x;  // 0..1023
    float s = 0.f;
#pragma unroll 8
    for (int p = 0; p < 96; ++p) s += g_partialC[p * 1024 + t];
    g_SC[t] = s;
}

// ---------------------------------------------------------------------------
// Kernel 3: S_x[b,h1,w2] = sum over rows r%8==h1, cols c%8==w2, all channels.
// Block = (b,h1) pair (1024 blocks), 192 threads, each a float4 of a 768-float
// row. 32 rows (stride 8) accumulated per thread, then a smem tree-reduce.
// Key invariant: a stride of S floats preserves the w2 bin iff 24 | S
// (24 floats = 8 cols * 3 ch). Strides 384,192,96,48,24 all qualify.
// ---------------------------------------------------------------------------
__global__ void sumX_kernel(const float* __restrict__ x) {
    __shared__ float sm[768];
    const int t  = threadIdx.x;          // 0..191 (float4 index within row)
    const int bh = blockIdx.x;           // b*8 + h1
    const int b  = bh >> 3;
    const int h1 = bh & 7;

    // float4 indexing: per-b = 49152 float4, per-row = 192 float4
    const float4* __restrict__ x4 = (const float4*)x;
    long base = (long)b * 49152 + (long)h1 * 192 + t;  // row h1, q=0

    float4 acc = make_float4(0.f, 0.f, 0.f, 0.f);
#pragma unroll 8
    for (int q = 0; q < 32; ++q) {
        float4 v = x4[base + (long)q * 1536];          // +8 rows per step
        acc.x += v.x; acc.y += v.y; acc.z += v.z; acc.w += v.w;
    }
    sm[4 * t + 0] = acc.x;
    sm[4 * t + 1] = acc.y;
    sm[4 * t + 2] = acc.z;
    sm[4 * t + 3] = acc.w;
    __syncthreads();

    // 768 -> 384 (stride 384 = 24*16, bin-safe). 192 threads handle 2 slots.
    sm[t]       += sm[t + 384];
    sm[t + 192] += sm[t + 576];
    __syncthreads();
    // 384 -> 192
    sm[t] += sm[t + 192];
    __syncthreads();
    // 192 -> 96
    if (t < 96) sm[t] += sm[t + 96];
    __syncthreads();
    // 96 -> 48
    if (t < 48) sm[t] += sm[t + 48];
    __syncthreads();
    // 48 -> 24
    if (t < 24) sm[t] += sm[t + 24];
    __syncthreads();
    // 24 floats left: positions f=0..23, bin w2 = f/3. Fold 3 channels.
    if (t < 8) {
        float s = sm[3 * t] + sm[3 * t + 1] + sm[3 * t + 2];
        g_SX[bh * 8 + t] = s;   // = b*64 + h1*8 + w2
    }
}

// ---------------------------------------------------------------------------
// Kernel 4: out[b,k,l,h,w] = S_C[k*4+l] * S_x[b*64+h*8+w]. float4 stores.
// out index o = b*65536 + (k*4+l)*64 + h*8 + w.
// ---------------------------------------------------------------------------
__global__ void expand_kernel(float* __restrict__ out) {
    const int idx = blockIdx.x * 256 + threadIdx.x;  // float4 index, 0..2097151
    const int o   = idx * 4;
    const int b   = o >> 16;
    const int kl  = (o >> 6) & 1023;
    const int hw4 = (o & 63) >> 2;

    const float  sc  = g_SC[kl];
    const float4 sx4 = ((const float4*)g_SX)[b * 16 + hw4];

    float4 r;
    r.x = sc * sx4.x; r.y = sc * sx4.y; r.z = sc * sx4.z; r.w = sc * sx4.w;
    ((float4*)out)[idx] = r;
}

// ---------------------------------------------------------------------------
extern "C" void kernel_launch(void* const* d_in, const int* in_sizes, int n_in,
                              void* d_out, int out_size) {
    const float* x = (const float*)d_in[0];  // [128,256,256,3]
    const float* C = (const float*)d_in[1];  // [768,4,256,4]
    float* out = (float*)d_out;              // [128,256,4,8,8]

    sumC_partial_kernel<<<96, 256>>>(C);
    sumC_final_kernel<<<4, 256>>>();
    sumX_kernel<<<1024, 192>>>(x);
    expand_kernel<<<8192, 256>>>(out);
}

// round 3
// speedup vs baseline: 1.3458x; 1.3458x over previous
#include <cuda_runtime.h>
#include <cuda_bf16.h>

// Scratch (allocation-free rule: __device__ globals)
__device__ float g_SC[1024];             // S_C[k*4+l]
__device__ float g_SX[128 * 64];         // S_x[b*64 + h*8 + w]

// ---------------------------------------------------------------------------
// Kernel 1 (fused reduce): 1152 blocks x 192 threads.
//   blocks [0,128):   full reduce of C columns -> g_SC (no second pass).
//                     block cid owns float4-cols {2cid, 2cid+1} over all 3072
//                     rows; per-thread 32 rows, then smem tree over 96 groups.
//   blocks [128,1152): sumX for one (b,h1): 32 rows x 768 floats binned into
//                     8 w2 sums via bin-safe strides (multiples of 24 floats).
// sumC blocks go FIRST so the (equal-sized) work packets co-run with sumX.
// ---------------------------------------------------------------------------
__global__ void reduce_kernel(const float* __restrict__ x,
                              const float* __restrict__ C) {
    __shared__ float sm[768];            // also viewed as float4 sm4[192]
    const int t = threadIdx.x;           // 0..191

    if (blockIdx.x < 128) {
        // ---------------- sumC ----------------
        float4* sm4 = (float4*)sm;       // [c(2)][rg(96)]
        const int cid = blockIdx.x;
        const int c  = t & 1;
        const int rg = t >> 1;           // 0..95
        const int c4 = 2 * cid + c;
        const float4* __restrict__ C4 = (const float4*)C;  // 256 f4 per row
        float4 acc = make_float4(0.f, 0.f, 0.f, 0.f);
#pragma unroll 8
        for (int q = 0; q < 32; ++q) {
            float4 v = C4[(rg + 96 * q) * 256 + c4];
            acc.x += v.x; acc.y += v.y; acc.z += v.z; acc.w += v.w;
        }
        sm4[c * 96 + rg] = acc;
        __syncthreads();
        // tree over rg: 96->48->24->12->6->3
        for (int s = 48; s >= 3; s >>= 1) {
            if (rg < s) {
                float4 a = sm4[c * 96 + rg];
                float4 bv = sm4[c * 96 + rg + s];
                a.x += bv.x; a.y += bv.y; a.z += bv.z; a.w += bv.w;
                sm4[c * 96 + rg] = a;
            }
            __syncthreads();
        }
        if (rg == 0) {
            float4 a0 = sm4[c * 96 + 0];
            float4 a1 = sm4[c * 96 + 1];
            float4 a2 = sm4[c * 96 + 2];
            float4 r;
            r.x = a0.x + a1.x + a2.x;
            r.y = a0.y + a1.y + a2.y;
            r.z = a0.z + a1.z + a2.z;
            r.w = a0.w + a1.w + a2.w;
            ((float4*)g_SC)[2 * cid + c] = r;
        }
        return;
    }

    // ---------------- sumX ----------------
    const int bh = blockIdx.x - 128;     // b*8 + h1
    const int b  = bh >> 3;
    const int h1 = bh & 7;

    const float4* __restrict__ x4 = (const float4*)x;   // 192 f4 per row
    long base = (long)b * 49152 + (long)h1 * 192 + t;   // row h1, q=0

    float4 acc = make_float4(0.f, 0.f, 0.f, 0.f);
#pragma unroll 8
    for (int q = 0; q < 32; ++q) {
        float4 v = x4[base + (long)q * 1536];            // +8 rows per step
        acc.x += v.x; acc.y += v.y; acc.z += v.z; acc.w += v.w;
    }
    sm[4 * t + 0] = acc.x;
    sm[4 * t + 1] = acc.y;
    sm[4 * t + 2] = acc.z;
    sm[4 * t + 3] = acc.w;
    __syncthreads();

    // 768 -> 384 (strides multiples of 24 floats preserve the w2 bin)
    sm[t]       += sm[t + 384];
    sm[t + 192] += sm[t + 576];
    __syncthreads();
    sm[t] += sm[t + 192];
    __syncthreads();
    if (t < 96) sm[t] += sm[t + 96];
    __syncthreads();
    if (t < 48) sm[t] += sm[t + 48];
    __syncthreads();
    if (t < 24) sm[t] += sm[t + 24];
    __syncthreads();
    if (t < 8) {
        float s = sm[3 * t] + sm[3 * t + 1] + sm[3 * t + 2];
        g_SX[bh * 8 + t] = s;            // = b*64 + h1*8 + w2
    }
}

// ---------------------------------------------------------------------------
// Kernel 2 (expand): out[b,kl,hw] = S_C[kl] * S_x[b,hw].
// 2048 blocks x 256 threads; each block owns 4096 consecutive floats (one b,
// 64 consecutive kl, all 64 hw). sc/sx staged in smem once; 4 float4 stores
// per thread (coalesced, stride 256 f4).
// ---------------------------------------------------------------------------
__global__ void expand_kernel(float* __restrict__ out) {
    __shared__ float  sc_s[64];
    __shared__ float4 sx_s[16];
    const int t   = threadIdx.x;
    const int blk = blockIdx.x;          // 0..2047
    const int b   = blk >> 4;            // 16 blocks per b
    const int kl0 = (blk & 15) * 64;

    if (t < 64)       sc_s[t]      = g_SC[kl0 + t];
    else if (t < 80)  sx_s[t - 64] = ((const float4*)g_SX)[b * 16 + (t - 64)];
    __syncthreads();

    float4* out4 = (float4*)out + (long)blk * 1024;
#pragma unroll
    for (int i = 0; i < 4; ++i) {
        const int j = t + 256 * i;       // 0..1023 (float4 within block)
        const float  sc = sc_s[j >> 4];
        const float4 sx = sx_s[j & 15];
        float4 r;
        r.x = sc * sx.x; r.y = sc * sx.y; r.z = sc * sx.z; r.w = sc * sx.w;
        out4[j] = r;
    }
}

// ---------------------------------------------------------------------------
extern "C" void kernel_launch(void* const* d_in, const int* in_sizes, int n_in,
                              void* d_out, int out_size) {
    const float* x = (const float*)d_in[0];  // [128,256,256,3]
    const float* C = (const float*)d_in[1];  // [768,4,256,4]
    float* out = (float*)d_out;              // [128,256,4,8,8]

    reduce_kernel<<<1152, 192>>>(x, C);
    expand_kernel<<<2048, 256>>>(out);
}